// round 9
// baseline (speedup 1.0000x reference)
#include <cuda_runtime.h>
#include <cuda.h>
#include <cuda_fp16.h>
#include <stdint.h>

#define MAXN    1048576        // >= 1,000,000 rows
#define KTAPS   27
#define CIN     32
#define COUT    32
#define MBLOCK  256            // rows per tile (2 m16-tiles x 16 rows per warp)
#define NTHREADS 256
#define NSTRIDE 260            // per-tap stride in nbr_s (x4B = 1040, 16B-aligned)
#define DEPTH   6              // TMA pipeline stages per warp

// Scratch (allocation-free): fp16 copy of X with permuted channel pairs, fp16 W.
__device__ __align__(128) __half g_x16[(size_t)MAXN * CIN];           // 64 MiB
__device__ __align__(16) __half g_w16[KTAPS * COUT * CIN];            // [tap][n][k'] 54 KiB
__device__ int g_nbr_is64;                                            // neighbor dtype flag
__device__ int g_tma_ok;                                              // gather4 self-test result

__device__ __forceinline__ int sigma(int s) { return ((s & 3) << 2) | (s >> 2); }

__device__ __forceinline__ uint32_t smem_u32(const void* p) {
    uint32_t a;
    asm("{ .reg .u64 t; cvta.to.shared.u64 t, %1; cvt.u32.u64 %0, t; }" : "=r"(a) : "l"(p));
    return a;
}

#define MBAR_INIT(mb, cnt) \
    asm volatile("mbarrier.init.shared.b64 [%0], %1;" :: "r"(mb), "r"(cnt) : "memory")
#define MBAR_EXPECT_TX(mb, bytes) \
    asm volatile("mbarrier.arrive.expect_tx.shared.b64 _, [%0], %1;" :: "r"(mb), "r"(bytes) : "memory")

__device__ __forceinline__ void mbar_wait(uint32_t mb, uint32_t parity) {
    uint32_t done;
    asm volatile("{\n\t.reg .pred p;\n\t"
        "mbarrier.try_wait.parity.acquire.cta.shared::cta.b64 p, [%1], %2;\n\t"
        "selp.b32 %0, 1, 0, p;\n\t}"
        : "=r"(done) : "r"(mb), "r"(parity) : "memory");
    if (!done) {
        asm volatile("{\n\t.reg .pred P1;\n\t"
            "WL_%=:\n\t"
            "mbarrier.try_wait.parity.acquire.cta.shared::cta.b64 P1, [%0], %1, 0x989680;\n\t"
            "@P1 bra.uni WD_%=;\n\t"
            "bra.uni WL_%=;\n\t"
            "WD_%=:\n\t}"
            :: "r"(mb), "r"(parity) : "memory");
    }
}

// sm_103: tile::gather4 requires .shared::cta destination (cluster form is gated off)
__device__ __forceinline__ void tma_gather4(uint32_t dst, const CUtensorMap* tm,
                                            int r0, int r1, int r2, int r3, uint32_t mb) {
    asm volatile(
        "cp.async.bulk.tensor.2d.shared::cta.global.tile::gather4.mbarrier::complete_tx::bytes "
        "[%0], [%1, {%2, %3, %4, %5, %6}], [%7];"
        :: "r"(dst), "l"(tm), "r"(0), "r"(r0), "r"(r1), "r"(r2), "r"(r3), "r"(mb) : "memory");
}

// ---------------- Neighbor dtype detection (tiny sample) ----------------
__global__ void detect_nbr_kernel(const int* __restrict__ words) {
    int nz = 0;
    #pragma unroll
    for (int j = 0; j < 8; j++)
        nz |= words[2 * (threadIdx.x * 8 + j) + 1];
    int any = __syncthreads_or(nz != 0);
    if (threadIdx.x == 0) g_nbr_is64 = any ? 0 : 1;
}

// ---------------- X conversion: fp32 [N,32] -> fp16 permuted [N,32] ----------------
__global__ void convert_x_kernel(const float* __restrict__ x, int n) {
    long long tid = (long long)blockIdx.x * blockDim.x + threadIdx.x;
    long long total = (long long)n * 16;
    if (tid >= total) return;
    int i = (int)(tid >> 4);
    int s = (int)(tid & 15);
    int p = sigma(s);
    float2 v = __ldcs((const float2*)(x + (size_t)i * CIN + 2 * p));
    ((__half2*)g_x16)[(size_t)i * 16 + s] = __floats2half2_rn(v.x, v.y);
}

// ---------------- W conversion: fp32 [tap][c][n] -> fp16 [tap][n][k'] ----------------
__global__ void convert_w_kernel(const float* __restrict__ w) {
    int e = blockIdx.x * blockDim.x + threadIdx.x;
    if (e >= KTAPS * COUT * CIN) return;
    int tap = e / (COUT * CIN);
    int rem = e % (COUT * CIN);
    int nn  = rem / CIN;
    int kp  = rem % CIN;
    int s   = kp >> 1, bit = kp & 1;
    int c   = 2 * sigma(s) + bit;
    g_w16[e] = __float2half_rn(w[(size_t)tap * CIN * COUT + (size_t)c * COUT + nn]);
}

// ---------------- gather4 self-test: gather 4 known rows, byte-compare ----------------
__global__ void tma_test_kernel(const __grid_constant__ CUtensorMap tmap, int n) {
    __shared__ __align__(1024) uint8_t buf[256];
    __shared__ uint64_t mbar_store;
    if (threadIdx.x != 0) return;
    uint32_t mb = smem_u32(&mbar_store);
    uint32_t db = smem_u32(buf);
    int rows[4] = {1, n / 3, n - 1, 0};
    MBAR_INIT(mb, 1);
    asm volatile("fence.proxy.async.shared::cta;" ::: "memory");
    MBAR_EXPECT_TX(mb, 256);
    tma_gather4(db, &tmap, rows[0], rows[1], rows[2], rows[3], mb);
    int ok = 0;
    for (int it = 0; it < 2000000 && !ok; it++) {
        uint32_t done;
        asm volatile("{\n\t.reg .pred p;\n\t"
            "mbarrier.try_wait.parity.acquire.cta.shared::cta.b64 p, [%1], %2;\n\t"
            "selp.b32 %0, 1, 0, p;\n\t}"
            : "=r"(done) : "r"(mb), "r"(0) : "memory");
        ok = (int)done;
    }
    if (ok) {
        const uint4* x4 = (const uint4*)g_x16;
        const uint4* b4 = (const uint4*)buf;
        for (int r = 0; r < 4; r++)
            for (int j = 0; j < 4; j++) {
                uint4 a = b4[r * 4 + j];
                uint4 c = x4[(size_t)rows[r] * 4 + j];
                if (a.x != c.x || a.y != c.y || a.z != c.z || a.w != c.w) ok = 0;
            }
    }
    g_tma_ok = ok;
}

// ---------------- fp16 MMA m16n8k16, fp32 accumulate ----------------
__device__ __forceinline__ void mma16816(float c[4],
                                         uint32_t a0, uint32_t a1, uint32_t a2, uint32_t a3,
                                         uint32_t b0, uint32_t b1) {
    asm("mma.sync.aligned.m16n8k16.row.col.f32.f16.f16.f32 "
        "{%0,%1,%2,%3}, {%4,%5,%6,%7}, {%8,%9}, {%0,%1,%2,%3};\n"
        : "+f"(c[0]), "+f"(c[1]), "+f"(c[2]), "+f"(c[3])
        : "r"(a0), "r"(a1), "r"(a2), "r"(a3), "r"(b0), "r"(b1));
}

// ---------------- Main kernel ----------------
// smem layout:
//   [0, 512)            48 mbarriers (8 warps x 6 stages)
//   [512, 56320)        fp16 W, 55296 B (uint4 view) + pad to 1024
//   [56320, 154624)     gather buffers: 8 warps x 6 stages x 2048 B
//   [154624, 182704)    int32 neighbor indices [27 taps][NSTRIDE]
#define MBAR_OFF   0
#define W_OFF      512
#define BUF_OFF    56320
#define NBR_OFF    154624
#define SMEM_BYTES (NBR_OFF + KTAPS * NSTRIDE * 4)

__global__ __launch_bounds__(NTHREADS, 1)
void conv_main_kernel(const void* __restrict__ nbr_raw,
                      const float* __restrict__ bias,
                      float* __restrict__ out, int n, int ntiles,
                      const __grid_constant__ CUtensorMap tmap) {
    extern __shared__ uint8_t smem[];
    uint4*   w_s4   = (uint4*)(smem + W_OFF);
    int*     nbr_s  = (int*)(smem + NBR_OFF);
    uint8_t* bufs   = smem + BUF_OFF;
    const uint32_t mbar0 = smem_u32(smem) + MBAR_OFF;
    const uint32_t buf0  = smem_u32(smem) + BUF_OFF;
    const CUtensorMap* tmp = &tmap;

    const int tid  = threadIdx.x;
    const int is64 = g_nbr_is64;
    const int tok  = g_tma_ok;

    if (tid < 8 * DEPTH) MBAR_INIT(mbar0 + tid * 8, 1);
    asm volatile("fence.proxy.async.shared::cta;" ::: "memory");

    // Stage W once per persistent block (3456 uint4, coalesced)
    const uint4* wg4 = (const uint4*)g_w16;
    #pragma unroll 4
    for (int t = tid; t < 3456; t += NTHREADS) w_s4[t] = wg4[t];
    __syncthreads();

    const int lane = tid & 31;
    const int warp = tid >> 5;
    const int q    = lane & 3;
    const int nrow = lane >> 2;
    const int mb   = warp * 32;    // warp's 32 rows within tile

    float2 bz[4];
    #pragma unroll
    for (int t = 0; t < 4; t++)
        bz[t] = *(const float2*)(bias + t * 8 + 2 * q);

    const char* xb = (const char*)g_x16 + q * 16;

    // TMA-path per-warp pipeline cursors (persist across tiles)
    unsigned gi = 0, gc = 0;

    // ---- TMA issue: one tap into stage gi%DEPTH ----
    #define ISSUE_TAP(kk) do {                                                   \
        int st_ = (int)(gi % DEPTH);                                             \
        uint32_t mb_ = mbar0 + (warp * DEPTH + st_) * 8;                         \
        uint32_t db_ = buf0 + (warp * DEPTH + st_) * 2048;                       \
        if (lane == 0) MBAR_EXPECT_TX(mb_, 2048);                                \
        __syncwarp();                                                            \
        if (lane < 8) {                                                          \
            int4 ri = *(const int4*)(nbr_s + (kk) * NSTRIDE + mb + lane * 4);    \
            tma_gather4(db_ + lane * 256, tmp, ri.x, ri.y, ri.z, ri.w, mb_);     \
        }                                                                        \
        gi++;                                                                    \
    } while (0)

    #define MMA_TAP4(k, lo0, hi0, lo1, hi1) do {                                 \
        _Pragma("unroll")                                                        \
        for (int t = 0; t < 4; t++) {                                            \
            uint4 bw = w_s4[(k) * 128 + (t * 8 + nrow) * 4 + q];                 \
            mma16816(acc[0][t], lo0.x, hi0.x, lo0.y, hi0.y, bw.x, bw.y);         \
            mma16816(acc[0][t], lo0.z, hi0.z, lo0.w, hi0.w, bw.z, bw.w);         \
            mma16816(acc[1][t], lo1.x, hi1.x, lo1.y, hi1.y, bw.x, bw.y);         \
            mma16816(acc[1][t], lo1.z, hi1.z, lo1.w, hi1.w, bw.z, bw.w);         \
        }                                                                        \
    } while (0)

    // LDG-path tap gather (fallback)
    #define LOAD_TAP_G(buf, k) do {                                              \
        _Pragma("unroll")                                                        \
        for (int mt = 0; mt < 2; mt++) {                                         \
            int ilo = nbr_s[(k) * NSTRIDE + mb + mt * 16 + nrow];                \
            int ihi = nbr_s[(k) * NSTRIDE + mb + mt * 16 + nrow + 8];            \
            (buf)[mt * 2 + 0] = *(const uint4*)(xb + ((size_t)(unsigned)ilo << 6)); \
            (buf)[mt * 2 + 1] = *(const uint4*)(xb + ((size_t)(unsigned)ihi << 6)); \
        }                                                                        \
    } while (0)

    for (int tile = blockIdx.x; tile < ntiles; tile += gridDim.x) {
        const int i0 = tile * MBLOCK;
        const bool full = (i0 + MBLOCK <= n);

        __syncthreads();   // all warps drained previous tile before nbr_s overwrite
        // Stage raw neighbor indices [tap][row]; independent iterations -> batched LDGs
        if (is64) {
            const long long* g = (const long long*)nbr_raw + (size_t)i0 * KTAPS + tid;
            #pragma unroll
            for (int j = 0; j < KTAPS; j++) {
                int t = tid + j * NTHREADS;
                int r = t / KTAPS;
                int k = t - r * KTAPS;
                long long v = (full || i0 + r < n) ? __ldcs(g + j * NTHREADS) : 0;
                nbr_s[k * NSTRIDE + r] = (int)v;
            }
        } else {
            const int* g = (const int*)nbr_raw + (size_t)i0 * KTAPS + tid;
            #pragma unroll
            for (int j = 0; j < KTAPS; j++) {
                int t = tid + j * NTHREADS;
                int r = t / KTAPS;
                int k = t - r * KTAPS;
                nbr_s[k * NSTRIDE + r] = (full || i0 + r < n) ? __ldcs(g + j * NTHREADS) : 0;
            }
        }
        __syncthreads();

        float acc[2][4][4];
        #pragma unroll
        for (int t = 0; t < 4; t++)
            #pragma unroll
            for (int mt = 0; mt < 2; mt++) {
                acc[mt][t][0] = bz[t].x; acc[mt][t][1] = bz[t].y;
                acc[mt][t][2] = bz[t].x; acc[mt][t][3] = bz[t].y;
            }

        if (tok) {
            // ---- TMA gather pipeline: per-warp depth-6 ----
            #pragma unroll
            for (int k = 0; k < DEPTH; k++) ISSUE_TAP(k);

            #pragma unroll 1
            for (int k = 0; k < KTAPS; k++) {
                int st = (int)(gc % DEPTH);
                uint32_t par = (uint32_t)((gc / DEPTH) & 1);
                gc++;
                mbar_wait(mbar0 + (warp * DEPTH + st) * 8, par);
                const uint8_t* wb = bufs + (warp * DEPTH + st) * 2048;
                uint4 lo0 = *(const uint4*)(wb + (nrow)      * 64 + q * 16);
                uint4 hi0 = *(const uint4*)(wb + (nrow + 8)  * 64 + q * 16);
                uint4 lo1 = *(const uint4*)(wb + (nrow + 16) * 64 + q * 16);
                uint4 hi1 = *(const uint4*)(wb + (nrow + 24) * 64 + q * 16);
                MMA_TAP4(k, lo0, hi0, lo1, hi1);
                // mma.sync converged => all lanes consumed this buffer; safe to reuse
                if (k + DEPTH < KTAPS) ISSUE_TAP(k + DEPTH);
            }
        } else {
            // ---- LDG fallback: depth-2, 3 rotating buffers (R7 scheme) ----
            uint4 A0[4], A1[4], A2[4];
            LOAD_TAP_G(A0, 0);
            LOAD_TAP_G(A1, 1);
            #pragma unroll 1
            for (int kk = 0; kk < KTAPS / 3; kk++) {
                int k = kk * 3;
                if (k + 2 < KTAPS) LOAD_TAP_G(A2, k + 2);
                MMA_TAP4(k, A0[0], A0[1], A0[2], A0[3]);
                if (k + 3 < KTAPS) LOAD_TAP_G(A0, k + 3);
                MMA_TAP4(k + 1, A1[0], A1[1], A1[2], A1[3]);
                if (k + 4 < KTAPS) LOAD_TAP_G(A1, k + 4);
                MMA_TAP4(k + 2, A2[0], A2[1], A2[2], A2[3]);
            }
        }

        // Epilogue: streaming stores (bias already in acc)
        #pragma unroll
        for (int mt = 0; mt < 2; mt++)
            #pragma unroll
            for (int half = 0; half < 2; half++) {
                int r = i0 + mb + mt * 16 + nrow + half * 8;
                if (full || r < n) {
                    float* po = out + (size_t)r * COUT + 2 * q;
                    #pragma unroll
                    for (int t = 0; t < 4; t++) {
                        float2 v;
                        v.x = acc[mt][t][half * 2 + 0];
                        v.y = acc[mt][t][half * 2 + 1];
                        __stcs((float2*)(po + t * 8), v);
                    }
                }
            }
    }
}

// ---------------- Launch ----------------
typedef CUresult (*PFN_encodeTiled)(CUtensorMap*, CUtensorMapDataType, cuuint32_t, void*,
                                    const cuuint64_t*, const cuuint64_t*, const cuuint32_t*,
                                    const cuuint32_t*, CUtensorMapInterleave, CUtensorMapSwizzle,
                                    CUtensorMapL2promotion, CUtensorMapFloatOOBfill);

extern "C" void kernel_launch(void* const* d_in, const int* in_sizes, int n_in,
                              void* d_out, int out_size) {
    const float* x    = (const float*)d_in[0];       // [N, 32] f32
    const float* w    = (const float*)d_in[1];       // [27, 32, 32] f32
    const float* bias = (const float*)d_in[2];       // [32] f32
    const void*  nbr  = d_in[3];                     // [N, 27] int32 OR int64 (detected)
    float*       out  = (float*)d_out;               // [N, 32] f32

    const int n = in_sizes[0] / CIN;
    const int ntiles = (n + MBLOCK - 1) / MBLOCK;

    int nsm = 148;
    cudaDeviceGetAttribute(&nsm, cudaDevAttrMultiProcessorCount, 0);
    int grid = nsm;
    if (grid > ntiles) grid = ntiles;

    // Build tensor map for g_x16 as [MAXN rows x 64 B], host-side CPU work only.
    static CUtensorMap tmap;   // zero-init static; overwritten below when encode works
    bool enc_ok = false;
    {
        void* xaddr = nullptr;
        cudaGetSymbolAddress(&xaddr, g_x16);
        PFN_encodeTiled fn = nullptr;
        cudaDriverEntryPointQueryResult qres;
        cudaGetDriverEntryPoint("cuTensorMapEncodeTiled", (void**)&fn,
                                cudaEnableDefault, &qres);
        if (fn && xaddr) {
            cuuint64_t dims[2]    = {64, MAXN};
            cuuint64_t strides[1] = {64};
            cuuint32_t box[2]     = {64, 1};
            cuuint32_t estr[2]    = {1, 1};
            CUresult r = fn(&tmap, CU_TENSOR_MAP_DATA_TYPE_UINT8, 2, xaddr,
                            dims, strides, box, estr,
                            CU_TENSOR_MAP_INTERLEAVE_NONE, CU_TENSOR_MAP_SWIZZLE_NONE,
                            CU_TENSOR_MAP_L2_PROMOTION_L2_128B,
                            CU_TENSOR_MAP_FLOAT_OOB_FILL_NONE);
            enc_ok = (r == CUDA_SUCCESS);
        }
    }

    cudaFuncSetAttribute(conv_main_kernel,
                         cudaFuncAttributeMaxDynamicSharedMemorySize, SMEM_BYTES);

    detect_nbr_kernel<<<1, 256>>>((const int*)nbr);
    {
        int total = KTAPS * COUT * CIN;
        convert_w_kernel<<<(total + NTHREADS - 1) / NTHREADS, NTHREADS>>>(w);
    }
    {
        long long total = (long long)n * 16;
        int blocks = (int)((total + NTHREADS - 1) / NTHREADS);
        convert_x_kernel<<<blocks, NTHREADS>>>(x, n);
    }
    if (enc_ok) {
        tma_test_kernel<<<1, 32>>>(tmap, n);
    } else {
        void* flagaddr = nullptr;
        cudaGetSymbolAddress(&flagaddr, g_tma_ok);
        cudaMemsetAsync(flagaddr, 0, sizeof(int));
    }
    conv_main_kernel<<<grid, NTHREADS, SMEM_BYTES>>>(nbr, bias, out, n, ntiles, tmap);
}

// round 10
// speedup vs baseline: 1.1060x; 1.1060x over previous
#include <cuda_runtime.h>
#include <cuda_fp16.h>
#include <stdint.h>

#define MAXN    1048576        // >= 1,000,000 rows
#define KTAPS   27
#define CIN     32
#define COUT    32
#define MBLOCK  256            // rows per tile (2 m16-tiles x 16 rows per warp)
#define NTHREADS 256

// Scratch (allocation-free): fp16 copy of X with permuted channel pairs, fp16 W.
__device__ __align__(128) __half g_x16[(size_t)MAXN * CIN];           // 64 MiB
__device__ __align__(16) __half g_w16[KTAPS * COUT * CIN];            // [tap][n][k'] 54 KiB
__device__ int g_nbr_is64;                                            // neighbor dtype flag

__device__ __forceinline__ int sigma(int s) { return ((s & 3) << 2) | (s >> 2); }

__device__ __forceinline__ uint32_t smem_u32(const void* p) {
    uint32_t a;
    asm("{ .reg .u64 t; cvta.to.shared.u64 t, %1; cvt.u32.u64 %0, t; }" : "=r"(a) : "l"(p));
    return a;
}

// ---------------- Neighbor dtype detection (tiny sample) ----------------
// int64 (values < 2^31, LE) -> all odd int32 words are 0; int32 -> random nonzero.
__global__ void detect_nbr_kernel(const int* __restrict__ words) {
    int nz = 0;
    #pragma unroll
    for (int j = 0; j < 8; j++)
        nz |= words[2 * (threadIdx.x * 8 + j) + 1];
    int any = __syncthreads_or(nz != 0);
    if (threadIdx.x == 0) g_nbr_is64 = any ? 0 : 1;
}

// ---------------- X conversion: fp32 [N,32] -> fp16 permuted [N,32] ----------------
__global__ void convert_x_kernel(const float* __restrict__ x, int n) {
    long long tid = (long long)blockIdx.x * blockDim.x + threadIdx.x;
    long long total = (long long)n * 16;
    if (tid >= total) return;
    int i = (int)(tid >> 4);
    int s = (int)(tid & 15);
    int p = sigma(s);
    float2 v = __ldcs((const float2*)(x + (size_t)i * CIN + 2 * p));
    ((__half2*)g_x16)[(size_t)i * 16 + s] = __floats2half2_rn(v.x, v.y);
}

// ---------------- W conversion: fp32 [tap][c][n] -> fp16 [tap][n][k'] ----------------
__global__ void convert_w_kernel(const float* __restrict__ w) {
    int e = blockIdx.x * blockDim.x + threadIdx.x;
    if (e >= KTAPS * COUT * CIN) return;
    int tap = e / (COUT * CIN);
    int rem = e % (COUT * CIN);
    int nn  = rem / CIN;
    int kp  = rem % CIN;
    int s   = kp >> 1, bit = kp & 1;
    int c   = 2 * sigma(s) + bit;
    g_w16[e] = __float2half_rn(w[(size_t)tap * CIN * COUT + (size_t)c * COUT + nn]);
}

// ---------------- fp16 MMA m16n8k16, fp32 accumulate ----------------
__device__ __forceinline__ void mma16816(float c[4],
                                         uint32_t a0, uint32_t a1, uint32_t a2, uint32_t a3,
                                         uint32_t b0, uint32_t b1) {
    asm("mma.sync.aligned.m16n8k16.row.col.f32.f16.f16.f32 "
        "{%0,%1,%2,%3}, {%4,%5,%6,%7}, {%8,%9}, {%0,%1,%2,%3};\n"
        : "+f"(c[0]), "+f"(c[1]), "+f"(c[2]), "+f"(c[3])
        : "r"(a0), "r"(a1), "r"(a2), "r"(a3), "r"(b0), "r"(b1));
}

// ---------------- Main: persistent, cp.async double-buffered staging ----------------
// smem: [0, 55296)              fp16 W (uint4 view)
//       [55296, +27648)         nbr buffer 0: int32 [256 rows][27 taps] row-major
//       [82944, +27648)         nbr buffer 1
#define W_SMEM      55296
#define STAGE_INTS  (MBLOCK * KTAPS)          // 6912
#define STAGE_BYTES (STAGE_INTS * 4)          // 27648
#define SMEM_BYTES  (W_SMEM + 2 * STAGE_BYTES)

__global__ __launch_bounds__(NTHREADS, 2)
void conv_main_kernel(const void* __restrict__ nbr_raw,
                      const float* __restrict__ bias,
                      float* __restrict__ out, int n, int ntiles) {
    extern __shared__ uint8_t smem[];
    uint4* w_s4 = (uint4*)smem;
    int*   nbuf[2] = { (int*)(smem + W_SMEM), (int*)(smem + W_SMEM + STAGE_BYTES) };
    const uint32_t nbufu[2] = { smem_u32(nbuf[0]), smem_u32(nbuf[1]) };

    const int tid  = threadIdx.x;
    const int is64 = g_nbr_is64;

    // Stage W once per persistent block (3456 uint4, coalesced)
    const uint4* wg4 = (const uint4*)g_w16;
    #pragma unroll 4
    for (int t = tid; t < 3456; t += NTHREADS) w_s4[t] = wg4[t];

    const int lane = tid & 31;
    const int warp = tid >> 5;
    const int q    = lane & 3;
    const int nrow = lane >> 2;
    const int mb   = warp * 32;                 // warp's 32 rows within tile
    const int rb   = (mb + nrow) * KTAPS;       // row base into nbr buffer

    float2 bz[4];
    #pragma unroll
    for (int t = 0; t < 4; t++)
        bz[t] = *(const float2*)(bias + t * 8 + 2 * q);

    const char* xb = (const char*)g_x16 + q * 16;

    // ---- staging: async fast path (int32, full tile), sync fallback otherwise ----
    #define STAGE_TILE(p_, tile_) do {                                              \
        const int i0_ = (tile_) * MBLOCK;                                           \
        if (!is64 && i0_ + MBLOCK <= n) {                                           \
            const char* src_ = (const char*)nbr_raw + (size_t)i0_ * KTAPS * 4;      \
            uint32_t dst_ = nbufu[p_];                                              \
            for (int t_ = tid; t_ < STAGE_BYTES / 16; t_ += NTHREADS)               \
                asm volatile("cp.async.cg.shared.global [%0], [%1], 16;"            \
                             :: "r"(dst_ + t_ * 16), "l"(src_ + (size_t)t_ * 16)    \
                             : "memory");                                           \
        } else if (is64) {                                                          \
            const long long* g_ = (const long long*)nbr_raw + (size_t)i0_ * KTAPS;  \
            for (int t_ = tid; t_ < STAGE_INTS; t_ += NTHREADS) {                   \
                long long v_ = (i0_ + t_ / KTAPS < n) ? __ldcs(g_ + t_) : 0;        \
                nbuf[p_][t_] = (int)v_;                                             \
            }                                                                       \
        } else {                                                                    \
            const int* g_ = (const int*)nbr_raw + (size_t)i0_ * KTAPS;              \
            for (int t_ = tid; t_ < STAGE_INTS; t_ += NTHREADS)                     \
                nbuf[p_][t_] = (i0_ + t_ / KTAPS < n) ? __ldcs(g_ + t_) : 0;        \
        }                                                                           \
        asm volatile("cp.async.commit_group;" ::: "memory");                        \
    } while (0)

    #define LOAD_TAP_G(buf, cur, k) do {                                            \
        _Pragma("unroll")                                                           \
        for (int mt = 0; mt < 2; mt++) {                                            \
            int ilo = (cur)[rb + mt * 16 * KTAPS + (k)];                            \
            int ihi = (cur)[rb + (mt * 16 + 8) * KTAPS + (k)];                      \
            (buf)[mt * 2 + 0] = *(const uint4*)(xb + ((size_t)(unsigned)ilo << 6)); \
            (buf)[mt * 2 + 1] = *(const uint4*)(xb + ((size_t)(unsigned)ihi << 6)); \
        }                                                                           \
    } while (0)

    #define MMA_TAP4(k, B_) do {                                                    \
        _Pragma("unroll")                                                           \
        for (int t = 0; t < 4; t++) {                                               \
            uint4 bw = w_s4[(k) * 128 + (t * 8 + nrow) * 4 + q];                    \
            mma16816(acc[0][t], B_[0].x, B_[1].x, B_[0].y, B_[1].y, bw.x, bw.y);    \
            mma16816(acc[0][t], B_[0].z, B_[1].z, B_[0].w, B_[1].w, bw.z, bw.w);    \
            mma16816(acc[1][t], B_[2].x, B_[3].x, B_[2].y, B_[3].y, bw.x, bw.y);    \
            mma16816(acc[1][t], B_[2].z, B_[3].z, B_[2].w, B_[3].w, bw.z, bw.w);    \
        }                                                                           \
    } while (0)

    int p = 0;
    const int tile0 = blockIdx.x;
    if (tile0 < ntiles) STAGE_TILE(0, tile0);

    for (int tile = tile0; tile < ntiles; tile += gridDim.x) {
        const int i0 = tile * MBLOCK;
        const bool full = (i0 + MBLOCK <= n);

        asm volatile("cp.async.wait_group 0;" ::: "memory");
        __syncthreads();   // buf[p] ready for all; all warps done reading buf[p^1]

        const int nxt = tile + gridDim.x;
        if (nxt < ntiles) STAGE_TILE(p ^ 1, nxt);

        const int* cur = nbuf[p];

        float acc[2][4][4];
        #pragma unroll
        for (int t = 0; t < 4; t++)
            #pragma unroll
            for (int mt = 0; mt < 2; mt++) {
                acc[mt][t][0] = bz[t].x; acc[mt][t][1] = bz[t].y;
                acc[mt][t][2] = bz[t].x; acc[mt][t][3] = bz[t].y;
            }

        // Depth-2 software pipeline, 3 rotating register buffers, KTAPS = 9*3.
        uint4 A0[4], A1[4], A2[4];
        LOAD_TAP_G(A0, cur, 0);
        LOAD_TAP_G(A1, cur, 1);
        #pragma unroll 1
        for (int kk = 0; kk < KTAPS / 3; kk++) {
            int k = kk * 3;
            if (k + 2 < KTAPS) LOAD_TAP_G(A2, cur, k + 2);
            MMA_TAP4(k, A0);
            if (k + 3 < KTAPS) LOAD_TAP_G(A0, cur, k + 3);
            MMA_TAP4(k + 1, A1);
            if (k + 4 < KTAPS) LOAD_TAP_G(A1, cur, k + 4);
            MMA_TAP4(k + 2, A2);
        }

        // Epilogue: streaming stores (bias already in acc)
        #pragma unroll
        for (int mt = 0; mt < 2; mt++)
            #pragma unroll
            for (int half = 0; half < 2; half++) {
                int r = i0 + mb + mt * 16 + nrow + half * 8;
                if (full || r < n) {
                    float* po = out + (size_t)r * COUT + 2 * q;
                    #pragma unroll
                    for (int t = 0; t < 4; t++) {
                        float2 v;
                        v.x = acc[mt][t][half * 2 + 0];
                        v.y = acc[mt][t][half * 2 + 1];
                        __stcs((float2*)(po + t * 8), v);
                    }
                }
            }

        p ^= 1;
    }
}

// ---------------- Launch ----------------
extern "C" void kernel_launch(void* const* d_in, const int* in_sizes, int n_in,
                              void* d_out, int out_size) {
    const float* x    = (const float*)d_in[0];       // [N, 32] f32
    const float* w    = (const float*)d_in[1];       // [27, 32, 32] f32
    const float* bias = (const float*)d_in[2];       // [32] f32
    const void*  nbr  = d_in[3];                     // [N, 27] int32 OR int64 (detected)
    float*       out  = (float*)d_out;               // [N, 32] f32

    const int n = in_sizes[0] / CIN;
    const int ntiles = (n + MBLOCK - 1) / MBLOCK;

    int nsm = 148;
    cudaDeviceGetAttribute(&nsm, cudaDevAttrMultiProcessorCount, 0);
    int grid = 2 * nsm;
    if (grid > ntiles) grid = ntiles;

    cudaFuncSetAttribute(conv_main_kernel,
                         cudaFuncAttributeMaxDynamicSharedMemorySize, SMEM_BYTES);

    detect_nbr_kernel<<<1, 256>>>((const int*)nbr);
    {
        int total = KTAPS * COUT * CIN;
        convert_w_kernel<<<(total + NTHREADS - 1) / NTHREADS, NTHREADS>>>(w);
    }
    {
        long long total = (long long)n * 16;
        int blocks = (int)((total + NTHREADS - 1) / NTHREADS);
        convert_x_kernel<<<blocks, NTHREADS>>>(x, n);
    }
    conv_main_kernel<<<grid, NTHREADS, SMEM_BYTES>>>(nbr, bias, out, n, ntiles);
}

// round 11
// speedup vs baseline: 1.7734x; 1.6034x over previous
#include <cuda_runtime.h>
#include <cuda_fp16.h>
#include <stdint.h>

#define MAXN    1048576        // >= 1,000,000 rows
#define KTAPS   27
#define CIN     32
#define COUT    32
#define MBLOCK  256            // rows per tile (2 m16-tiles x 16 rows per warp)
#define NTHREADS 256

// Scratch (allocation-free): fp16 copy of X with permuted channel pairs, fp16 W.
__device__ __align__(128) __half g_x16[(size_t)MAXN * CIN];           // 64 MiB
__device__ __align__(16) __half g_w16[KTAPS * COUT * CIN];            // [tap][n][k'] 54 KiB
__device__ int g_nbr_is64;                                            // neighbor dtype flag

// Involution on channel-pair index (s in 0..15): sigma(sigma(s)) == s
__device__ __forceinline__ int sigma(int s) { return ((s & 3) << 2) | (s >> 2); }

// ---------------- Fused prep: X convert + W convert + nbr dtype detect ----------------
// Grid sized for X conversion (n*16 threads). Blocks < 108 additionally convert one
// 256-element chunk of W. Block 0 additionally runs the dtype detector. All three
// are independent; the main kernel follows in-stream.
__global__ void prep_kernel(const float* __restrict__ x,
                            const float* __restrict__ w,
                            const int*   __restrict__ nbr_words, int n) {
    // --- X conversion: fp32 [N,32] -> fp16 permuted [N,32] ---
    long long tid = (long long)blockIdx.x * blockDim.x + threadIdx.x;
    long long total = (long long)n * 16;
    if (tid < total) {
        int i = (int)(tid >> 4);
        int s = (int)(tid & 15);
        int p = sigma(s);                      // memory slot s holds original pair sigma(s)
        float2 v = __ldcs((const float2*)(x + (size_t)i * CIN + 2 * p));
        ((__half2*)g_x16)[(size_t)i * 16 + s] = __floats2half2_rn(v.x, v.y);
    }

    // --- W conversion: fp32 [tap][c][n] -> fp16 [tap][n][k'] (first 108 blocks) ---
    if (blockIdx.x < (KTAPS * COUT * CIN + NTHREADS - 1) / NTHREADS) {
        int e = blockIdx.x * NTHREADS + threadIdx.x;
        if (e < KTAPS * COUT * CIN) {
            int tap = e / (COUT * CIN);
            int rem = e % (COUT * CIN);
            int nn  = rem / CIN;
            int kp  = rem % CIN;               // permuted k position
            int s   = kp >> 1, bit = kp & 1;
            int c   = 2 * sigma(s) + bit;      // original input channel
            g_w16[e] = __float2half_rn(w[(size_t)tap * CIN * COUT + (size_t)c * COUT + nn]);
        }
    }

    // --- nbr dtype detect (block 0): int64 LE nonneg -> odd int32 words all zero ---
    if (blockIdx.x == 0) {
        int nz = 0;
        #pragma unroll
        for (int j = 0; j < 8; j++)
            nz |= nbr_words[2 * (threadIdx.x * 8 + j) + 1];
        int any = __syncthreads_or(nz != 0);
        if (threadIdx.x == 0) g_nbr_is64 = any ? 0 : 1;
    }
}

// ---------------- fp16 MMA m16n8k16, fp32 accumulate ----------------
__device__ __forceinline__ void mma16816(float c[4],
                                         uint32_t a0, uint32_t a1, uint32_t a2, uint32_t a3,
                                         uint32_t b0, uint32_t b1) {
    asm("mma.sync.aligned.m16n8k16.row.col.f32.f16.f16.f32 "
        "{%0,%1,%2,%3}, {%4,%5,%6,%7}, {%8,%9}, {%0,%1,%2,%3};\n"
        : "+f"(c[0]), "+f"(c[1]), "+f"(c[2]), "+f"(c[3])
        : "r"(a0), "r"(a1), "r"(a2), "r"(a3), "r"(b0), "r"(b1));
}

// ---------------- Main: persistent blocks, gather + 27-tap MMA, depth-2 pipeline ----
// (Reverted verbatim to the R5 configuration: best measured main = 242.4 us.)
// smem: [0, 55296)          fp16 W (uint4 view, [tap][n-tile-row][16B])
//       [55296, 82944)      int32 neighbor BYTE OFFSETS (idx*64) [256 rows][27 taps]
#define W_SMEM     55296
#define SMEM_BYTES (W_SMEM + MBLOCK * KTAPS * 4)

__global__ __launch_bounds__(NTHREADS, 2)
void conv_main_kernel(const void* __restrict__ nbr_raw,
                      const float* __restrict__ bias,
                      float* __restrict__ out, int n, int ntiles) {
    extern __shared__ uint8_t smem[];
    uint4* w_s4  = (uint4*)smem;
    int*   nbr_s = (int*)(smem + W_SMEM);

    const int tid  = threadIdx.x;
    const int is64 = g_nbr_is64;

    // Stage W once per persistent block (3456 uint4, coalesced)
    const uint4* wg4 = (const uint4*)g_w16;
    #pragma unroll 4
    for (int t = tid; t < 3456; t += NTHREADS) w_s4[t] = wg4[t];

    const int lane = tid & 31;
    const int warp = tid >> 5;
    const int q    = lane & 3;     // quad column (16B chunk within row)
    const int nrow = lane >> 2;    // 0..7
    const int mb   = warp * 32;    // warp's 32 rows within tile

    // Bias fragment (kept in regs across tiles)
    float2 bz[4];
    #pragma unroll
    for (int t = 0; t < 4; t++)
        bz[t] = *(const float2*)(bias + t * 8 + 2 * q);

    const char* xb = (const char*)g_x16 + q * 16;   // this thread's chunk base

    #define LOAD_TAP(buf, k) do {                                           \
        _Pragma("unroll")                                                   \
        for (int mt = 0; mt < 2; mt++) {                                    \
            int rlo = mb + mt * 16 + nrow;                                  \
            int olo = nbr_s[rlo * KTAPS + (k)];                             \
            int ohi = nbr_s[(rlo + 8) * KTAPS + (k)];                       \
            (buf)[mt * 2 + 0] = *(const uint4*)(xb + olo);                  \
            (buf)[mt * 2 + 1] = *(const uint4*)(xb + ohi);                  \
        }                                                                   \
    } while (0)

    #define MMA_TAP(buf, k) do {                                            \
        _Pragma("unroll")                                                   \
        for (int t = 0; t < 4; t++) {                                       \
            uint4 bw = w_s4[(k) * 128 + (t * 8 + nrow) * 4 + q];            \
            _Pragma("unroll")                                               \
            for (int mt = 0; mt < 2; mt++) {                                \
                const uint4& lo = (buf)[mt * 2 + 0];                        \
                const uint4& hi = (buf)[mt * 2 + 1];                        \
                mma16816(acc[mt][t], lo.x, hi.x, lo.y, hi.y, bw.x, bw.y);   \
                mma16816(acc[mt][t], lo.z, hi.z, lo.w, hi.w, bw.z, bw.w);   \
            }                                                               \
        }                                                                   \
    } while (0)

    for (int tile = blockIdx.x; tile < ntiles; tile += gridDim.x) {
        const int i0 = tile * MBLOCK;

        __syncthreads();   // previous tile's readers done before nbr_s overwrite
        // Stage neighbor byte-offsets (idx*64), coalesced, tail-guarded.
        if (is64) {
            const long long* nbr = (const long long*)nbr_raw;
            for (int t = tid; t < MBLOCK * KTAPS; t += NTHREADS) {
                int r = t / KTAPS;
                long long v = (i0 + r < n) ? __ldcs(nbr + (size_t)i0 * KTAPS + t) : 0;
                nbr_s[t] = ((int)v) << 6;
            }
        } else {
            const int* nbr = (const int*)nbr_raw;
            for (int t = tid; t < MBLOCK * KTAPS; t += NTHREADS) {
                int r = t / KTAPS;
                int v = (i0 + r < n) ? __ldcs(nbr + (size_t)i0 * KTAPS + t) : 0;
                nbr_s[t] = v << 6;
            }
        }
        __syncthreads();

        // Acc init = bias
        float acc[2][4][4];
        #pragma unroll
        for (int t = 0; t < 4; t++) {
            #pragma unroll
            for (int mt = 0; mt < 2; mt++) {
                acc[mt][t][0] = bz[t].x; acc[mt][t][1] = bz[t].y;
                acc[mt][t][2] = bz[t].x; acc[mt][t][3] = bz[t].y;
            }
        }

        // Depth-2 software pipeline, 3 rotating register buffers, KTAPS = 9*3.
        uint4 A0[4], A1[4], A2[4];
        LOAD_TAP(A0, 0);
        LOAD_TAP(A1, 1);

        #pragma unroll 1
        for (int kk = 0; kk < KTAPS / 3; kk++) {
            int k = kk * 3;
            if (k + 2 < KTAPS) LOAD_TAP(A2, k + 2);
            MMA_TAP(A0, k);
            if (k + 3 < KTAPS) LOAD_TAP(A0, k + 3);
            MMA_TAP(A1, k + 1);
            if (k + 4 < KTAPS) LOAD_TAP(A1, k + 4);
            MMA_TAP(A2, k + 2);
        }

        // Epilogue: streaming stores (bias already in acc)
        #pragma unroll
        for (int mt = 0; mt < 2; mt++) {
            #pragma unroll
            for (int half = 0; half < 2; half++) {
                int r = i0 + mb + mt * 16 + nrow + half * 8;
                if (r < n) {
                    float* po = out + (size_t)r * COUT + 2 * q;
                    #pragma unroll
                    for (int t = 0; t < 4; t++) {
                        float2 v;
                        v.x = acc[mt][t][half * 2 + 0];
                        v.y = acc[mt][t][half * 2 + 1];
                        __stcs((float2*)(po + t * 8), v);
                    }
                }
            }
        }
    }
}

// ---------------- Launch ----------------
extern "C" void kernel_launch(void* const* d_in, const int* in_sizes, int n_in,
                              void* d_out, int out_size) {
    const float* x    = (const float*)d_in[0];       // [N, 32] f32
    const float* w    = (const float*)d_in[1];       // [27, 32, 32] f32
    const float* bias = (const float*)d_in[2];       // [32] f32
    const void*  nbr  = d_in[3];                     // [N, 27] int32 OR int64 (detected)
    float*       out  = (float*)d_out;               // [N, 32] f32

    const int n = in_sizes[0] / CIN;
    const int ntiles = (n + MBLOCK - 1) / MBLOCK;

    int nsm = 148;
    cudaDeviceGetAttribute(&nsm, cudaDevAttrMultiProcessorCount, 0);
    int grid = 2 * nsm;
    if (grid > ntiles) grid = ntiles;

    cudaFuncSetAttribute(conv_main_kernel,
                         cudaFuncAttributeMaxDynamicSharedMemorySize, SMEM_BYTES);

    {
        long long total = (long long)n * 16;
        int blocks = (int)((total + NTHREADS - 1) / NTHREADS);
        prep_kernel<<<blocks, NTHREADS>>>(x, w, (const int*)nbr, n);
    }
    conv_main_kernel<<<grid, NTHREADS, SMEM_BYTES>>>(nbr, bias, out, n, ntiles);
}